// round 2
// baseline (speedup 1.0000x reference)
#include <cuda_runtime.h>
#include <cstdint>

#define BB 32
#define CC 64
#define TT_FULL 16384
#define KW 21
#define TCV (TT_FULL - KW + 1)   /* 16364 */
#define TTILE 64
#define NTILES ((TCV + TTILE - 1) / TTILE)  /* 256 */

typedef unsigned long long ull;

// ---------------- device scratch (no allocations allowed) ----------------
__device__ float g_y1[BB * CC * TT_FULL];          // raw conv1 output (padded T stride)
__device__ float g_y2[BB * CC * TT_FULL];          // raw conv2 output
__device__ ull   g_wtp[2][CC * CC * KW];           // weights transposed [i][o][k], packed {w,w}
__device__ double g_sum[2][CC];
__device__ double g_sq[2][CC];
__device__ float g_feat[BB * 384];

__device__ __forceinline__ void ffma2(ull& acc, ull a, ull w) {
    asm("fma.rn.f32x2 %0, %1, %2, %0;" : "+l"(acc) : "l"(a), "l"(w));
}
__device__ __forceinline__ float f2lo(ull v) { return __uint_as_float((unsigned)v); }
__device__ __forceinline__ float f2hi(ull v) { return __uint_as_float((unsigned)(v >> 32)); }

// ---------------- prep kernels ----------------
__global__ void zero_stats_k() {
    int t = threadIdx.x;
    if (t < 128) { ((double*)g_sum)[t] = 0.0; ((double*)g_sq)[t] = 0.0; }
}

__global__ void pack_weights_k(const float* __restrict__ w1, const float* __restrict__ w2) {
    int gid = blockIdx.x * blockDim.x + threadIdx.x;
    const int per = CC * CC * KW;  // 86016
    if (gid >= 2 * per) return;
    int conv = gid / per;
    int r = gid % per;
    int i = r / (CC * KW);
    int q = r % (CC * KW);
    int o = q / KW;
    int k = q % KW;
    const float* w = conv ? w2 : w1;
    unsigned u = __float_as_uint(w[(o * CC + i) * KW + k]);
    g_wtp[conv][r] = ((ull)u << 32) | (ull)u;
}

// ---------------- conv kernel (even/odd polyphase, fma.rn.f32x2) ----------------
// block: 256 threads. o = tid>>2 (64 out channels), tg = tid&3 (4 groups of 16 t).
// Each thread: 16 output positions, one output channel, one conv.
__global__ void __launch_bounds__(256) conv_k(const float* __restrict__ x) {
    __shared__ __align__(16) float xs[CC][84];     // 64 x (TTILE + 20) = 21.5 KB
    __shared__ ull ws[2][CC * KW];                 // double-buffered weight slice, 21 KB
    __shared__ float s_sum[CC];
    __shared__ float s_sq[CC];

    const int tid  = threadIdx.x;
    const int tile = blockIdx.x;
    const int b    = blockIdx.y;
    const int conv = blockIdx.z;
    const int t0   = tile * TTILE;

    // stage x tile (coalesced)
    for (int idx = tid; idx < CC * 84; idx += 256) {
        int i = idx / 84, j = idx % 84;
        int t = t0 + j;
        xs[i][j] = (t < TT_FULL) ? x[(b * CC + i) * TT_FULL + t] : 0.f;
    }
    const ull* wt = g_wtp[conv];
    for (int idx = tid; idx < CC * KW; idx += 256) ws[0][idx] = wt[idx];
    __syncthreads();

    const int o = tid >> 2;
    const int tg = tid & 3;
    const int base = tg * 16;

    ull accE[8], accO[9];
#pragma unroll
    for (int p = 0; p < 8; p++) accE[p] = 0ULL;
#pragma unroll
    for (int j = 0; j < 9; j++) accO[j] = 0ULL;

    int buf = 0;
#pragma unroll 1
    for (int i = 0; i < CC; i++) {
        // prefetch next weight slice into registers (hides L2 latency behind FMAs)
        ull pre[6];
        const bool do_pre = (i + 1 < CC);
        if (do_pre) {
            const ull* src = wt + (i + 1) * (CC * KW);
#pragma unroll
            for (int u = 0; u < 6; u++) {
                int idx = tid + u * 256;
                if (idx < CC * KW) pre[u] = src[idx];
            }
        }

        // load 36 x values = 18 aligned pairs via 9x LDS.128
        ull Xe[18];
        const ulonglong2* xp = reinterpret_cast<const ulonglong2*>(&xs[i][base]);
#pragma unroll
        for (int m = 0; m < 9; m++) { ulonglong2 v = xp[m]; Xe[2 * m] = v.x; Xe[2 * m + 1] = v.y; }

        const ull* w = &ws[buf][o * KW];
        // even taps: accE[p] = {y[2p], y[2p+1]}
#pragma unroll
        for (int kk = 0; kk <= 10; kk++) {
            ull wk = w[2 * kk];
#pragma unroll
            for (int p = 0; p < 8; p++) ffma2(accE[p], Xe[p + kk], wk);
        }
        // odd taps: accO[j] = {y[2j-1], y[2j]}
#pragma unroll
        for (int kk = 0; kk <= 9; kk++) {
            ull wk = w[2 * kk + 1];
#pragma unroll
            for (int j = 0; j < 9; j++) ffma2(accO[j], Xe[j + kk], wk);
        }

        if (do_pre) {
#pragma unroll
            for (int u = 0; u < 6; u++) {
                int idx = tid + u * 256;
                if (idx < CC * KW) ws[buf ^ 1][idx] = pre[u];
            }
        }
        __syncthreads();
        buf ^= 1;
    }

    // combine polyphase accumulators
    float yv[16];
#pragma unroll
    for (int p = 0; p < 8; p++) {
        yv[2 * p]     = f2lo(accE[p]) + f2hi(accO[p]);
        yv[2 * p + 1] = f2hi(accE[p]) + f2lo(accO[p + 1]);
    }

    float* yout = (conv ? g_y2 : g_y1) + (size_t)(b * CC + o) * TT_FULL + t0 + base;
    float lsum = 0.f, lsq = 0.f;
    const int tstart = t0 + base;
    if (tstart + 16 <= TCV) {
#pragma unroll
        for (int q = 0; q < 4; q++) {
            float4 v = make_float4(yv[4 * q], yv[4 * q + 1], yv[4 * q + 2], yv[4 * q + 3]);
            reinterpret_cast<float4*>(yout)[q] = v;
        }
#pragma unroll
        for (int q = 0; q < 16; q++) { lsum += yv[q]; lsq += yv[q] * yv[q]; }
    } else {
#pragma unroll
        for (int q = 0; q < 16; q++) {
            if (tstart + q < TCV) { yout[q] = yv[q]; lsum += yv[q]; lsq += yv[q] * yv[q]; }
        }
    }

    // per-channel partial stats -> shared -> global double atomics
    if (tid < CC) { s_sum[tid] = 0.f; s_sq[tid] = 0.f; }
    __syncthreads();
    atomicAdd(&s_sum[o], lsum);
    atomicAdd(&s_sq[o], lsq);
    __syncthreads();
    if (tid < CC) {
        atomicAdd(&g_sum[conv][tid], (double)s_sum[tid]);
        atomicAdd(&g_sq[conv][tid], (double)s_sq[tid]);
    }
}

// ---------------- pooling kernel: BN + LeakyReLU + SPP windows ----------------
__global__ void __launch_bounds__(256) pool_k(const int* __restrict__ orig_len,
                                              const float* __restrict__ g1, const float* __restrict__ b1,
                                              const float* __restrict__ g2, const float* __restrict__ b2) {
    const int c = blockIdx.x, b = blockIdx.y;
    const int tid = threadIdx.x;
    const int L = orig_len[b] - (KW - 1);
    const int strd = L >> 1;         // floor(L/2)
    const int kern = L - strd;       // ceil(L/2)

    const double CNT = (double)BB * (double)TCV;
    double m1 = g_sum[0][c] / CNT;
    double v1 = g_sq[0][c] / CNT - m1 * m1;
    double m2 = g_sum[1][c] / CNT;
    double v2 = g_sq[1][c] / CNT - m2 * m2;
    const float sc1 = (float)((double)g1[c] / sqrt(v1 + 1e-5));
    const float sh1 = (float)((double)b1[c] - m1 * ((double)g1[c] / sqrt(v1 + 1e-5)));
    const float sc2 = (float)((double)g2[c] / sqrt(v2 + 1e-5));
    const float sh2 = (float)((double)b2[c] - m2 * ((double)g2[c] / sqrt(v2 + 1e-5)));

    const float* y1r = g_y1 + (size_t)(b * CC + c) * TT_FULL;
    const float* y2r = g_y2 + (size_t)(b * CC + c) * TT_FULL;

    const float NEG = -3.402823466e38f;
    float mx0 = NEG, mx1 = NEG, mx2 = NEG;
    float s0 = 0.f, s1 = 0.f, s2 = 0.f;
    for (int t = tid; t < L; t += 256) {
        float z1 = sc1 * y1r[t] + sh1; z1 = (z1 > 0.f) ? z1 : 0.01f * z1;
        mx0 = fmaxf(mx0, z1);
        if (t < kern) mx1 = fmaxf(mx1, z1);
        if (t >= strd) mx2 = fmaxf(mx2, z1);
        float z2 = sc2 * y2r[t] + sh2; z2 = (z2 > 0.f) ? z2 : 0.01f * z2;
        s0 += z2;
        if (t < kern) s1 += z2;
        if (t >= strd) s2 += z2;
    }
    // warp reduce
#pragma unroll
    for (int off = 16; off; off >>= 1) {
        mx0 = fmaxf(mx0, __shfl_down_sync(0xffffffffu, mx0, off));
        mx1 = fmaxf(mx1, __shfl_down_sync(0xffffffffu, mx1, off));
        mx2 = fmaxf(mx2, __shfl_down_sync(0xffffffffu, mx2, off));
        s0 += __shfl_down_sync(0xffffffffu, s0, off);
        s1 += __shfl_down_sync(0xffffffffu, s1, off);
        s2 += __shfl_down_sync(0xffffffffu, s2, off);
    }
    __shared__ float red[8][6];
    if ((tid & 31) == 0) {
        int w = tid >> 5;
        red[w][0] = mx0; red[w][1] = mx1; red[w][2] = mx2;
        red[w][3] = s0;  red[w][4] = s1;  red[w][5] = s2;
    }
    __syncthreads();
    if (tid == 0) {
        float a0 = red[0][0], a1 = red[0][1], a2 = red[0][2];
        float t0 = red[0][3], t1 = red[0][4], t2 = red[0][5];
#pragma unroll
        for (int w = 1; w < 8; w++) {
            a0 = fmaxf(a0, red[w][0]); a1 = fmaxf(a1, red[w][1]); a2 = fmaxf(a2, red[w][2]);
            t0 += red[w][3]; t1 += red[w][4]; t2 += red[w][5];
        }
        float* f = g_feat + b * 384;
        // p1 (max branch): level0 [c], level1 [64 + 2c + j]
        f[c] = a0;
        f[64 + 2 * c]     = a1;
        f[64 + 2 * c + 1] = a2;
        // p2 (avg branch): offset 192
        f[192 + c] = t0 / (float)L;
        f[192 + 64 + 2 * c]     = t1 / (float)kern;
        f[192 + 64 + 2 * c + 1] = t2 / (float)kern;
    }
}

// ---------------- FC head ----------------
__global__ void fc_k(const float* __restrict__ fc_w, const float* __restrict__ fc_b,
                     float* __restrict__ out) {
    int tid = threadIdx.x;
    if (tid >= BB * 2) return;
    int b = tid >> 1, task = tid & 1;
    const float* f = g_feat + b * 384;
    const float* w = fc_w + task * 384;
    float acc = fc_b[task];
#pragma unroll 8
    for (int j = 0; j < 384; j++) acc += f[j] * w[j];
    out[b * 2 + task] = acc;
}

// ---------------- launch ----------------
extern "C" void kernel_launch(void* const* d_in, const int* in_sizes, int n_in,
                              void* d_out, int out_size) {
    const float* x        = (const float*)d_in[0];
    const int*   orig_len = (const int*)d_in[1];
    const float* w1   = (const float*)d_in[2];
    const float* g1   = (const float*)d_in[3];
    const float* b1   = (const float*)d_in[4];
    const float* w2   = (const float*)d_in[5];
    const float* g2   = (const float*)d_in[6];
    const float* b2   = (const float*)d_in[7];
    const float* fc_w = (const float*)d_in[8];
    const float* fc_b = (const float*)d_in[9];
    float* out = (float*)d_out;

    zero_stats_k<<<1, 128>>>();
    pack_weights_k<<<(2 * CC * CC * KW + 255) / 256, 256>>>(w1, w2);

    dim3 cgrid(NTILES, BB, 2);
    conv_k<<<cgrid, 256>>>(x);

    dim3 pgrid(CC, BB);
    pool_k<<<pgrid, 256>>>(orig_len, g1, b1, g2, b2);

    fc_k<<<1, 64>>>(fc_w, fc_b, out);
}

// round 5
// speedup vs baseline: 1.0009x; 1.0009x over previous
#include <cuda_runtime.h>
#include <cstdint>

#define BB 32
#define CC 64
#define TT_FULL 16384
#define KW 21
#define TCV (TT_FULL - KW + 1)   /* 16364 */
#define TTILE 64
#define NTILES ((TCV + TTILE - 1) / TTILE)  /* 256 */

typedef unsigned long long ull;

// ---------------- device scratch (no allocations allowed) ----------------
__device__ float g_y1[BB * CC * TT_FULL];          // raw conv1 output (padded T stride)
__device__ float g_y2[BB * CC * TT_FULL];          // raw conv2 output
__device__ ull   g_wtp[2][CC * CC * KW];           // weights transposed [i][o][k], packed {w,w}
__device__ double g_sum[2][CC];
__device__ double g_sq[2][CC];
__device__ float g_feat[BB * 384];

__device__ __forceinline__ void ffma2(ull& acc, ull a, ull w) {
    asm("fma.rn.f32x2 %0, %1, %2, %0;" : "+l"(acc) : "l"(a), "l"(w));
}
__device__ __forceinline__ float f2lo(ull v) { return __uint_as_float((unsigned)v); }
__device__ __forceinline__ float f2hi(ull v) { return __uint_as_float((unsigned)(v >> 32)); }

// ---------------- prep kernels ----------------
__global__ void zero_stats_k() {
    int t = threadIdx.x;
    if (t < 128) { ((double*)g_sum)[t] = 0.0; ((double*)g_sq)[t] = 0.0; }
}

__global__ void pack_weights_k(const float* __restrict__ w1, const float* __restrict__ w2) {
    int gid = blockIdx.x * blockDim.x + threadIdx.x;
    const int per = CC * CC * KW;  // 86016
    if (gid >= 2 * per) return;
    int conv = gid / per;
    int r = gid % per;
    int i = r / (CC * KW);
    int q = r % (CC * KW);
    int o = q / KW;
    int k = q % KW;
    const float* w = conv ? w2 : w1;
    unsigned u = __float_as_uint(w[(o * CC + i) * KW + k]);
    g_wtp[conv][r] = ((ull)u << 32) | (ull)u;
}

// ---------------- conv kernel (even/odd polyphase, fma.rn.f32x2) ----------------
// block: 256 threads. o = tid>>2 (64 out channels), tg = tid&3 (4 groups of 16 t).
// Each thread: 16 output positions, one output channel, one conv.
__global__ void __launch_bounds__(256) conv_k(const float* __restrict__ x) {
    __shared__ __align__(16) float xs[CC][84];     // 64 x (TTILE + 20) = 21.5 KB
    __shared__ ull ws[2][CC * KW];                 // double-buffered weight slice, 21 KB
    __shared__ float s_sum[CC];
    __shared__ float s_sq[CC];

    const int tid  = threadIdx.x;
    const int tile = blockIdx.x;
    const int b    = blockIdx.y;
    const int conv = blockIdx.z;
    const int t0   = tile * TTILE;

    // stage x tile (coalesced)
    for (int idx = tid; idx < CC * 84; idx += 256) {
        int i = idx / 84, j = idx % 84;
        int t = t0 + j;
        xs[i][j] = (t < TT_FULL) ? x[(b * CC + i) * TT_FULL + t] : 0.f;
    }
    const ull* wt = g_wtp[conv];
    for (int idx = tid; idx < CC * KW; idx += 256) ws[0][idx] = wt[idx];
    __syncthreads();

    const int o = tid >> 2;
    const int tg = tid & 3;
    const int base = tg * 16;

    ull accE[8], accO[9];
#pragma unroll
    for (int p = 0; p < 8; p++) accE[p] = 0ULL;
#pragma unroll
    for (int j = 0; j < 9; j++) accO[j] = 0ULL;

    int buf = 0;
#pragma unroll 1
    for (int i = 0; i < CC; i++) {
        // prefetch next weight slice into registers (hides L2 latency behind FMAs)
        ull pre[6];
        const bool do_pre = (i + 1 < CC);
        if (do_pre) {
            const ull* src = wt + (i + 1) * (CC * KW);
#pragma unroll
            for (int u = 0; u < 6; u++) {
                int idx = tid + u * 256;
                if (idx < CC * KW) pre[u] = src[idx];
            }
        }

        // load 36 x values = 18 aligned pairs via 9x LDS.128
        ull Xe[18];
        const ulonglong2* xp = reinterpret_cast<const ulonglong2*>(&xs[i][base]);
#pragma unroll
        for (int m = 0; m < 9; m++) { ulonglong2 v = xp[m]; Xe[2 * m] = v.x; Xe[2 * m + 1] = v.y; }

        const ull* w = &ws[buf][o * KW];
        // even taps: accE[p] = {y[2p], y[2p+1]}
#pragma unroll
        for (int kk = 0; kk <= 10; kk++) {
            ull wk = w[2 * kk];
#pragma unroll
            for (int p = 0; p < 8; p++) ffma2(accE[p], Xe[p + kk], wk);
        }
        // odd taps: accO[j] = {y[2j-1], y[2j]}
#pragma unroll
        for (int kk = 0; kk <= 9; kk++) {
            ull wk = w[2 * kk + 1];
#pragma unroll
            for (int j = 0; j < 9; j++) ffma2(accO[j], Xe[j + kk], wk);
        }

        if (do_pre) {
#pragma unroll
            for (int u = 0; u < 6; u++) {
                int idx = tid + u * 256;
                if (idx < CC * KW) ws[buf ^ 1][idx] = pre[u];
            }
        }
        __syncthreads();
        buf ^= 1;
    }

    // combine polyphase accumulators
    float yv[16];
#pragma unroll
    for (int p = 0; p < 8; p++) {
        yv[2 * p]     = f2lo(accE[p]) + f2hi(accO[p]);
        yv[2 * p + 1] = f2hi(accE[p]) + f2lo(accO[p + 1]);
    }

    float* yout = (conv ? g_y2 : g_y1) + (size_t)(b * CC + o) * TT_FULL + t0 + base;
    float lsum = 0.f, lsq = 0.f;
    const int tstart = t0 + base;
    if (tstart + 16 <= TCV) {
#pragma unroll
        for (int q = 0; q < 4; q++) {
            float4 v = make_float4(yv[4 * q], yv[4 * q + 1], yv[4 * q + 2], yv[4 * q + 3]);
            reinterpret_cast<float4*>(yout)[q] = v;
        }
#pragma unroll
        for (int q = 0; q < 16; q++) { lsum += yv[q]; lsq += yv[q] * yv[q]; }
    } else {
#pragma unroll
        for (int q = 0; q < 16; q++) {
            if (tstart + q < TCV) { yout[q] = yv[q]; lsum += yv[q]; lsq += yv[q] * yv[q]; }
        }
    }

    // per-channel partial stats -> shared -> global double atomics
    if (tid < CC) { s_sum[tid] = 0.f; s_sq[tid] = 0.f; }
    __syncthreads();
    atomicAdd(&s_sum[o], lsum);
    atomicAdd(&s_sq[o], lsq);
    __syncthreads();
    if (tid < CC) {
        atomicAdd(&g_sum[conv][tid], (double)s_sum[tid]);
        atomicAdd(&g_sq[conv][tid], (double)s_sq[tid]);
    }
}

// ---------------- pooling kernel: BN + LeakyReLU + SPP windows ----------------
__global__ void __launch_bounds__(256) pool_k(const int* __restrict__ orig_len,
                                              const float* __restrict__ g1, const float* __restrict__ b1,
                                              const float* __restrict__ g2, const float* __restrict__ b2) {
    const int c = blockIdx.x, b = blockIdx.y;
    const int tid = threadIdx.x;
    const int L = orig_len[b] - (KW - 1);
    const int strd = L >> 1;         // floor(L/2)
    const int kern = L - strd;       // ceil(L/2)

    const double CNT = (double)BB * (double)TCV;
    double m1 = g_sum[0][c] / CNT;
    double v1 = g_sq[0][c] / CNT - m1 * m1;
    double m2 = g_sum[1][c] / CNT;
    double v2 = g_sq[1][c] / CNT - m2 * m2;
    const float sc1 = (float)((double)g1[c] / sqrt(v1 + 1e-5));
    const float sh1 = (float)((double)b1[c] - m1 * ((double)g1[c] / sqrt(v1 + 1e-5)));
    const float sc2 = (float)((double)g2[c] / sqrt(v2 + 1e-5));
    const float sh2 = (float)((double)b2[c] - m2 * ((double)g2[c] / sqrt(v2 + 1e-5)));

    const float* y1r = g_y1 + (size_t)(b * CC + c) * TT_FULL;
    const float* y2r = g_y2 + (size_t)(b * CC + c) * TT_FULL;

    const float NEG = -3.402823466e38f;
    float mx0 = NEG, mx1 = NEG, mx2 = NEG;
    float s0 = 0.f, s1 = 0.f, s2 = 0.f;
    for (int t = tid; t < L; t += 256) {
        float z1 = sc1 * y1r[t] + sh1; z1 = (z1 > 0.f) ? z1 : 0.01f * z1;
        mx0 = fmaxf(mx0, z1);
        if (t < kern) mx1 = fmaxf(mx1, z1);
        if (t >= strd) mx2 = fmaxf(mx2, z1);
        float z2 = sc2 * y2r[t] + sh2; z2 = (z2 > 0.f) ? z2 : 0.01f * z2;
        s0 += z2;
        if (t < kern) s1 += z2;
        if (t >= strd) s2 += z2;
    }
    // warp reduce
#pragma unroll
    for (int off = 16; off; off >>= 1) {
        mx0 = fmaxf(mx0, __shfl_down_sync(0xffffffffu, mx0, off));
        mx1 = fmaxf(mx1, __shfl_down_sync(0xffffffffu, mx1, off));
        mx2 = fmaxf(mx2, __shfl_down_sync(0xffffffffu, mx2, off));
        s0 += __shfl_down_sync(0xffffffffu, s0, off);
        s1 += __shfl_down_sync(0xffffffffu, s1, off);
        s2 += __shfl_down_sync(0xffffffffu, s2, off);
    }
    __shared__ float red[8][6];
    if ((tid & 31) == 0) {
        int w = tid >> 5;
        red[w][0] = mx0; red[w][1] = mx1; red[w][2] = mx2;
        red[w][3] = s0;  red[w][4] = s1;  red[w][5] = s2;
    }
    __syncthreads();
    if (tid == 0) {
        float a0 = red[0][0], a1 = red[0][1], a2 = red[0][2];
        float t0 = red[0][3], t1 = red[0][4], t2 = red[0][5];
#pragma unroll
        for (int w = 1; w < 8; w++) {
            a0 = fmaxf(a0, red[w][0]); a1 = fmaxf(a1, red[w][1]); a2 = fmaxf(a2, red[w][2]);
            t0 += red[w][3]; t1 += red[w][4]; t2 += red[w][5];
        }
        float* f = g_feat + b * 384;
        // p1 (max branch): level0 [c], level1 [64 + 2c + j]
        f[c] = a0;
        f[64 + 2 * c]     = a1;
        f[64 + 2 * c + 1] = a2;
        // p2 (avg branch): offset 192
        f[192 + c] = t0 / (float)L;
        f[192 + 64 + 2 * c]     = t1 / (float)kern;
        f[192 + 64 + 2 * c + 1] = t2 / (float)kern;
    }
}

// ---------------- FC head ----------------
__global__ void fc_k(const float* __restrict__ fc_w, const float* __restrict__ fc_b,
                     float* __restrict__ out) {
    int tid = threadIdx.x;
    if (tid >= BB * 2) return;
    int b = tid >> 1, task = tid & 1;
    const float* f = g_feat + b * 384;
    const float* w = fc_w + task * 384;
    float acc = fc_b[task];
#pragma unroll 8
    for (int j = 0; j < 384; j++) acc += f[j] * w[j];
    out[b * 2 + task] = acc;
}

// ---------------- launch ----------------
extern "C" void kernel_launch(void* const* d_in, const int* in_sizes, int n_in,
                              void* d_out, int out_size) {
    const float* x        = (const float*)d_in[0];
    const int*   orig_len = (const int*)d_in[1];
    const float* w1   = (const float*)d_in[2];
    const float* g1   = (const float*)d_in[3];
    const float* b1   = (const float*)d_in[4];
    const float* w2   = (const float*)d_in[5];
    const float* g2   = (const float*)d_in[6];
    const float* b2   = (const float*)d_in[7];
    const float* fc_w = (const float*)d_in[8];
    const float* fc_b = (const float*)d_in[9];
    float* out = (float*)d_out;

    zero_stats_k<<<1, 128>>>();
    pack_weights_k<<<(2 * CC * CC * KW + 255) / 256, 256>>>(w1, w2);

    dim3 cgrid(NTILES, BB, 2);
    conv_k<<<cgrid, 256>>>(x);

    dim3 pgrid(CC, BB);
    pool_k<<<pgrid, 256>>>(orig_len, g1, b1, g2, b2);

    fc_k<<<1, 64>>>(fc_w, fc_b, out);
}